// round 1
// baseline (speedup 1.0000x reference)
#include <cuda_runtime.h>
#include <cuda_bf16.h>
#include <math.h>

// Problem constants
#define Bn 2
#define Sn 2048
#define Dn 1024
#define Hn 16
#define DKn 64
#define FDn 64
#define Mrows (Bn*Sn)     // 4096

// ---------------- scratch (no allocs allowed) ----------------
__device__ float g_Q[Mrows * Dn];
__device__ float g_K[Mrows * Dn];
__device__ float g_V[Mrows * Dn];
__device__ float g_A[Mrows * Dn];
__device__ float g_Fn[Bn * Sn * FDn];
__device__ float g_Rn[Bn * Sn * FDn];

// ---------------- l2 normalize (warp per row of 64) ----------------
__global__ __launch_bounds__(256) void l2norm_kernel(
    const float* __restrict__ feat, const float* __restrict__ req,
    float* __restrict__ featn, float* __restrict__ reqn)
{
    int warp = (blockIdx.x * blockDim.x + threadIdx.x) >> 5;
    int lane = threadIdx.x & 31;
    if (warp >= 2 * Bn * Sn) return;
    const float* src; float* dst; int row;
    if (warp < Bn * Sn) { src = feat; dst = featn; row = warp; }
    else                { src = req;  dst = reqn;  row = warp - Bn * Sn; }
    float2 v = ((const float2*)src)[row * 32 + lane];
    float ss = v.x * v.x + v.y * v.y;
    #pragma unroll
    for (int o = 16; o; o >>= 1) ss += __shfl_xor_sync(0xffffffffu, ss, o);
    float inv = 1.0f / fmaxf(sqrtf(ss), 1e-12f);
    ((float2*)dst)[row * 32 + lane] = make_float2(v.x * inv, v.y * inv);
}

// ---------------- fp32 SGEMM: C = A[4096,1024] * W[1024,1024] + bias ----------------
// 128x128 tile, BK=8, 256 threads, 8x8 microtile. gridDim.z selects (W,b,C) triple.
#define BM 128
#define BN 128
#define BKK 8
__global__ __launch_bounds__(256, 2) void sgemm3(
    const float* __restrict__ A,
    const float* __restrict__ W0, const float* __restrict__ W1, const float* __restrict__ W2,
    const float* __restrict__ b0, const float* __restrict__ b1, const float* __restrict__ b2,
    float* __restrict__ C0, float* __restrict__ C1, float* __restrict__ C2)
{
    const int Kd = Dn, Nd = Dn;
    const float* __restrict__ W    = (blockIdx.z == 0) ? W0 : (blockIdx.z == 1) ? W1 : W2;
    const float* __restrict__ bias = (blockIdx.z == 0) ? b0 : (blockIdx.z == 1) ? b1 : b2;
    float* __restrict__ C          = (blockIdx.z == 0) ? C0 : (blockIdx.z == 1) ? C1 : C2;

    __shared__ float As[BKK][BM + 4];   // transposed, padded (conflict-free stores)
    __shared__ float Bs[BKK][BN];

    int tid = threadIdx.x;
    int tx = tid & 15, ty = tid >> 4;
    int m0 = blockIdx.y * BM, n0 = blockIdx.x * BN;

    float acc[8][8];
    #pragma unroll
    for (int i = 0; i < 8; i++)
        #pragma unroll
        for (int j = 0; j < 8; j++) acc[i][j] = 0.0f;

    int arow = tid >> 1;            // 0..127
    int akq  = (tid & 1) * 4;       // 0 or 4
    int brow = tid >> 5;            // 0..7
    int bcol = (tid & 31) * 4;

    const float* Aptr = A + (size_t)(m0 + arow) * Kd + akq;
    const float* Wptr = W + (size_t)brow * Nd + n0 + bcol;

    for (int k0 = 0; k0 < Kd; k0 += BKK) {
        float4 av = *(const float4*)(Aptr + k0);
        float4 bv = *(const float4*)(Wptr + (size_t)k0 * Nd);
        As[akq + 0][arow] = av.x;
        As[akq + 1][arow] = av.y;
        As[akq + 2][arow] = av.z;
        As[akq + 3][arow] = av.w;
        *(float4*)&Bs[brow][bcol] = bv;
        __syncthreads();
        #pragma unroll
        for (int kk = 0; kk < BKK; kk++) {
            float ar[8], br[8];
            *(float4*)&ar[0] = *(const float4*)&As[kk][ty * 8];
            *(float4*)&ar[4] = *(const float4*)&As[kk][ty * 8 + 4];
            *(float4*)&br[0] = *(const float4*)&Bs[kk][tx * 8];
            *(float4*)&br[4] = *(const float4*)&Bs[kk][tx * 8 + 4];
            #pragma unroll
            for (int i = 0; i < 8; i++)
                #pragma unroll
                for (int j = 0; j < 8; j++)
                    acc[i][j] += ar[i] * br[j];
        }
        __syncthreads();
    }

    float bb[8];
    *(float4*)&bb[0] = *(const float4*)&bias[n0 + tx * 8];
    *(float4*)&bb[4] = *(const float4*)&bias[n0 + tx * 8 + 4];
    #pragma unroll
    for (int i = 0; i < 8; i++) {
        size_t row = (size_t)(m0 + ty * 8 + i);
        float4 o0 = make_float4(acc[i][0] + bb[0], acc[i][1] + bb[1],
                                acc[i][2] + bb[2], acc[i][3] + bb[3]);
        float4 o1 = make_float4(acc[i][4] + bb[4], acc[i][5] + bb[5],
                                acc[i][6] + bb[6], acc[i][7] + bb[7]);
        *(float4*)&C[row * Nd + n0 + tx * 8]     = o0;
        *(float4*)&C[row * Nd + n0 + tx * 8 + 4] = o1;
    }
}

// ---------------- flash attention with fused ASA bias ----------------
// Per block: 64 query rows x 64 key cols per iteration, 256 threads (16x16), 4x4 microtiles.
// Qext = [Q/8, req_n] (128 dims), Kext = [K, feat_n] -> S = Qext . Kext^T directly
// includes the bias term.
#define QPAD 132
#define VPAD 68
#define PPAD 65
#define QS_OFF 0
#define KS_OFF (64 * QPAD)                 // 8448
#define VS_OFF (KS_OFF + 64 * QPAD)        // 16896
#define PS_OFF (VS_OFF + 64 * VPAD)        // 21248
#define SMEM_FLOATS (PS_OFF + 64 * PPAD)   // 25408
#define SMEM_BYTES (SMEM_FLOATS * 4)       // 101632

__global__ __launch_bounds__(256) void attn_kernel(
    const float* __restrict__ Q, const float* __restrict__ K, const float* __restrict__ V,
    const float* __restrict__ featn, const float* __restrict__ reqn,
    float* __restrict__ Oout)
{
    extern __shared__ float sm[];
    float* Qs = sm + QS_OFF;
    float* Ks = sm + KS_OFF;
    float* Vs = sm + VS_OFF;
    float* Ps = sm + PS_OFF;

    int tid = threadIdx.x;
    int tx = tid & 15, ty = tid >> 4;
    int m0t = gridDim.x - 1 - blockIdx.x;    // largest tiles first
    int h = blockIdx.y, b = blockIdx.z;
    int qbase = m0t * 64;
    int browbase = b * Sn;

    // ---- load Qext tile: [64][128] (Q/8 | req_n) ----
    for (int idx = tid; idx < 64 * 32; idx += 256) {
        int r = idx >> 5;
        int d = (idx & 31) * 4;
        int grow = browbase + qbase + r;
        float4 v;
        if (d < 64) {
            v = *(const float4*)&Q[(size_t)grow * Dn + h * DKn + d];
            v.x *= 0.125f; v.y *= 0.125f; v.z *= 0.125f; v.w *= 0.125f;
        } else {
            v = *(const float4*)&reqn[(size_t)grow * FDn + (d - 64)];
        }
        *(float4*)&Qs[r * QPAD + d] = v;
    }

    float o[4][4];
    #pragma unroll
    for (int i = 0; i < 4; i++)
        #pragma unroll
        for (int j = 0; j < 4; j++) o[i][j] = 0.0f;
    float mrow[4], lrow[4];
    #pragma unroll
    for (int i = 0; i < 4; i++) { mrow[i] = -1e30f; lrow[i] = 0.0f; }

    for (int jt = 0; jt <= m0t; jt++) {
        int kbase = jt * 64;
        // ---- load Kext tile + V tile ----
        for (int idx = tid; idx < 64 * 32; idx += 256) {
            int c = idx >> 5;
            int d = (idx & 31) * 4;
            int grow = browbase + kbase + c;
            float4 v;
            if (d < 64) v = *(const float4*)&K[(size_t)grow * Dn + h * DKn + d];
            else        v = *(const float4*)&featn[(size_t)grow * FDn + (d - 64)];
            *(float4*)&Ks[c * QPAD + d] = v;
        }
        for (int idx = tid; idx < 64 * 16; idx += 256) {
            int c = idx >> 4;
            int d = (idx & 15) * 4;
            int grow = browbase + kbase + c;
            *(float4*)&Vs[c * VPAD + d] =
                *(const float4*)&V[(size_t)grow * Dn + h * DKn + d];
        }
        __syncthreads();

        // ---- S tile: s[i][j] = Qext[r] . Kext[c] ----
        float s[4][4];
        #pragma unroll
        for (int i = 0; i < 4; i++)
            #pragma unroll
            for (int j = 0; j < 4; j++) s[i][j] = 0.0f;

        #pragma unroll 8
        for (int d = 0; d < 128; d += 4) {
            float4 q[4], k[4];
            #pragma unroll
            for (int i = 0; i < 4; i++)
                q[i] = *(const float4*)&Qs[(ty * 4 + i) * QPAD + d];
            #pragma unroll
            for (int j = 0; j < 4; j++)
                k[j] = *(const float4*)&Ks[(tx * 4 + j) * QPAD + d];
            #pragma unroll
            for (int i = 0; i < 4; i++)
                #pragma unroll
                for (int j = 0; j < 4; j++)
                    s[i][j] += q[i].x * k[j].x + q[i].y * k[j].y +
                               q[i].z * k[j].z + q[i].w * k[j].w;
        }

        // ---- causal mask on diagonal tile ----
        if (jt == m0t) {
            #pragma unroll
            for (int i = 0; i < 4; i++)
                #pragma unroll
                for (int j = 0; j < 4; j++)
                    if ((tx * 4 + j) > (ty * 4 + i)) s[i][j] = -1e30f;
        }

        // ---- online softmax update (per row, reduce over 16 lanes) ----
        #pragma unroll
        for (int i = 0; i < 4; i++) {
            float tm = fmaxf(fmaxf(s[i][0], s[i][1]), fmaxf(s[i][2], s[i][3]));
            #pragma unroll
            for (int off = 1; off < 16; off <<= 1)
                tm = fmaxf(tm, __shfl_xor_sync(0xffffffffu, tm, off));
            float mnew = fmaxf(mrow[i], tm);
            float corr = __expf(mrow[i] - mnew);
            float rs = 0.0f;
            #pragma unroll
            for (int j = 0; j < 4; j++) {
                float p = __expf(s[i][j] - mnew);
                s[i][j] = p;
                rs += p;
            }
            #pragma unroll
            for (int off = 1; off < 16; off <<= 1)
                rs += __shfl_xor_sync(0xffffffffu, rs, off);
            lrow[i] = lrow[i] * corr + rs;
            mrow[i] = mnew;
            #pragma unroll
            for (int j = 0; j < 4; j++) o[i][j] *= corr;
        }

        // ---- P to smem ----
        #pragma unroll
        for (int i = 0; i < 4; i++)
            #pragma unroll
            for (int j = 0; j < 4; j++)
                Ps[(ty * 4 + i) * PPAD + tx * 4 + j] = s[i][j];
        __syncthreads();

        // ---- O += P * V ----
        #pragma unroll 8
        for (int c = 0; c < 64; c++) {
            float4 v = *(const float4*)&Vs[c * VPAD + tx * 4];
            float pc[4];
            #pragma unroll
            for (int i = 0; i < 4; i++) pc[i] = Ps[(ty * 4 + i) * PPAD + c];
            #pragma unroll
            for (int i = 0; i < 4; i++) {
                o[i][0] += pc[i] * v.x;
                o[i][1] += pc[i] * v.y;
                o[i][2] += pc[i] * v.z;
                o[i][3] += pc[i] * v.w;
            }
        }
        __syncthreads();   // protect Ks/Vs/Ps before next tile load
    }

    // ---- epilogue ----
    #pragma unroll
    for (int i = 0; i < 4; i++) {
        float inv = 1.0f / lrow[i];
        int grow = browbase + qbase + ty * 4 + i;
        float4 ov = make_float4(o[i][0] * inv, o[i][1] * inv,
                                o[i][2] * inv, o[i][3] * inv);
        *(float4*)&Oout[(size_t)grow * Dn + h * DKn + tx * 4] = ov;
    }
}

// ---------------- launch ----------------
extern "C" void kernel_launch(void* const* d_in, const int* in_sizes, int n_in,
                              void* d_out, int out_size)
{
    const float* x    = (const float*)d_in[0];
    const float* feat = (const float*)d_in[1];
    const float* req  = (const float*)d_in[2];
    const float* Wq   = (const float*)d_in[3];
    const float* bq   = (const float*)d_in[4];
    const float* Wk   = (const float*)d_in[5];
    const float* bk   = (const float*)d_in[6];
    const float* Wv   = (const float*)d_in[7];
    const float* bv   = (const float*)d_in[8];
    const float* Wo   = (const float*)d_in[9];
    const float* bo   = (const float*)d_in[10];
    // d_in[11] pos_ids, d_in[12] causal_mask: unused (mask is deterministic tril)
    float* out = (float*)d_out;

    float *gQ, *gK, *gV, *gA, *gFn, *gRn;
    cudaGetSymbolAddress((void**)&gQ,  g_Q);
    cudaGetSymbolAddress((void**)&gK,  g_K);
    cudaGetSymbolAddress((void**)&gV,  g_V);
    cudaGetSymbolAddress((void**)&gA,  g_A);
    cudaGetSymbolAddress((void**)&gFn, g_Fn);
    cudaGetSymbolAddress((void**)&gRn, g_Rn);

    cudaFuncSetAttribute(attn_kernel,
                         cudaFuncAttributeMaxDynamicSharedMemorySize, SMEM_BYTES);

    // 1) normalize features / requirements
    l2norm_kernel<<<(2 * Bn * Sn) / 8, 256>>>(feat, req, gFn, gRn);

    // 2) Q/K/V projections (fused via gridDim.z)
    sgemm3<<<dim3(Dn / BN, Mrows / BM, 3), 256>>>(
        x, Wq, Wk, Wv, bq, bk, bv, gQ, gK, gV);

    // 3) causal flash attention with fused ASA bias
    attn_kernel<<<dim3(Sn / 64, Hn, Bn), 256, SMEM_BYTES>>>(
        gQ, gK, gV, gFn, gRn, gA);

    // 4) output projection -> d_out
    sgemm3<<<dim3(Dn / BN, Mrows / BM, 1), 256>>>(
        gA, Wo, Wo, Wo, bo, bo, bo, out, out, out);
}